// round 12
// baseline (speedup 1.0000x reference)
#include <cuda_runtime.h>

// CRF NLL mean — B=256, S=512, T=64.
// Bidirectional split (fwd: transitions 1..255, bwd: 511..256), combined at the
// midpoint:  Z_b = sum_j f_j(255) * v_j(255) * 2^(eoff_f + eoff_b).
// Each chain = ONE self-contained warp (no inter-warp barriers). Block =
// 128 thr = 2 batches x {fwd,bwd}; grid = 128 -> 1 block/SM, 1 warp/SMSP.
// Parity-split f32x2 accumulation: A-operand is the naturally packed pair
// (u_{2k}, u_{2k+1}); output j = acc.lo + acc.hi. 16 LDS.128 + 64 FMA2 / step.

constexpr int NT  = 64;
constexpr int NB  = 256;
constexpr int NS  = 512;
constexpr int MID = 256;

__device__ float g_llh[NB];
__device__ int   g_cnt = 0;

#define FMA2(d,a,b,c) asm("fma.rn.f32x2 %0, %1, %2, %3;" : "=l"(d) : "l"(a), "l"(b), "l"(c))
#define MUL2(d,a,b)   asm("mul.rn.f32x2 %0, %1, %2;"     : "=l"(d) : "l"(a), "l"(b))
#define ADD2(d,a,b)   asm("add.rn.f32x2 %0, %1, %2;"     : "=l"(d) : "l"(a), "l"(b))
#define PACK2(d,lo,hi)   asm("mov.b64 %0, {%1, %2};" : "=l"(d) : "f"(lo), "f"(hi))
#define UNPACK2(lo,hi,s) asm("mov.b64 {%0, %1}, %2;" : "=f"(lo), "=f"(hi) : "l"(s))

__device__ __forceinline__ float warp_sum_f(float v) {
#pragma unroll
    for (int o = 16; o > 0; o >>= 1) v += __shfl_down_sync(0xffffffffu, v, o);
    return v;
}
__device__ __forceinline__ int warp_sum_i(int v) {
#pragma unroll
    for (int o = 16; o > 0; o >>= 1) v += __shfl_down_sync(0xffffffffu, v, o);
    return v;
}

// Full 64-contraction for outputs (j0, j1) with parity-split accumulators.
// pb holds the packed u vector (64 floats). EpA/EpB: EpA[k] = (E[2k][j0], E[2k+1][j0]).
__device__ __forceinline__ void dot_full(
    const float* __restrict__ pb,
    const unsigned long long* __restrict__ EpA,
    const unsigned long long* __restrict__ EpB,
    float& outA, float& outB)
{
    unsigned long long a0=0ull,a1=0ull,a2=0ull,a3=0ull;
    unsigned long long b0=0ull,b1=0ull,b2=0ull,b3=0ull;
    const ulonglong2* p2 = (const ulonglong2*)pb;   // 16 x 16B, broadcast
#pragma unroll
    for (int g = 0; g < 16; g += 2) {
        ulonglong2 q0 = p2[g];          // (u_{4g..4g+3})
        ulonglong2 q1 = p2[g + 1];
        FMA2(a0, q0.x, EpA[2*g + 0], a0);
        FMA2(b0, q0.x, EpB[2*g + 0], b0);
        FMA2(a1, q0.y, EpA[2*g + 1], a1);
        FMA2(b1, q0.y, EpB[2*g + 1], b1);
        FMA2(a2, q1.x, EpA[2*g + 2], a2);
        FMA2(b2, q1.x, EpB[2*g + 2], b2);
        FMA2(a3, q1.y, EpA[2*g + 3], a3);
        FMA2(b3, q1.y, EpB[2*g + 3], b3);
    }
    ADD2(a0, a0, a1); ADD2(a2, a2, a3); ADD2(a0, a0, a2);
    ADD2(b0, b0, b1); ADD2(b2, b2, b3); ADD2(b0, b0, b2);
    float lo, hi;
    UNPACK2(lo, hi, a0); outA = lo + hi;
    UNPACK2(lo, hi, b0); outB = lo + hi;
}

__global__ __launch_bounds__(128, 1) void crf_forward_kernel(
    const float* __restrict__ em,        // (B,S,T)
    const int*   __restrict__ tags32,    // (B,S) int32 (or int64 viewed as pairs)
    const int*   __restrict__ mask,      // (B,S)
    const float* __restrict__ startT,
    const float* __restrict__ endT,
    const float* __restrict__ trans,
    float*       __restrict__ out)
{
    const int tid = threadIdx.x;
    const int w   = tid >> 5;            // warp 0..3 -> SMSP 0..3
    const int t   = tid & 31;            // lane; owns outputs j0=2t, j1=2t+1
    const int bs  = w >> 1;              // batch slot (0/1)
    const int dir = w & 1;               // 0 = forward, 1 = backward
    const int b   = blockIdx.x * 2 + bs;

    // per-warp double-buffered packed u vector (64 floats = 256B)
    __shared__ __align__(16) float ubuf[4][2][NT];
    __shared__ float fv[2][2][NT];       // [bs][dir][tag] midpoint vectors
    __shared__ float nsh[4];
    __shared__ int   msh[4], eosh[4];

    // tag dtype probe (int64 => every odd i32 word is zero hi-word)
    bool is64 = true;
#pragma unroll
    for (int k = 0; k < 16; k++) is64 &= (tags32[2 * k + 1] == 0);

    const int j0 = 2 * t, j1 = 2 * t + 1;

    // E pairs over the contraction dim, parity-packed (128 regs total)
    unsigned long long EpA[32], EpB[32];
    if (dir == 0) {
        // fwd: contraction over i (rows), outputs = columns j0/j1
#pragma unroll
        for (int k = 0; k < 32; k++) {
            float eA0 = __expf(trans[(2 * k)     * NT + j0]);
            float eA1 = __expf(trans[(2 * k + 1) * NT + j0]);
            float eB0 = __expf(trans[(2 * k)     * NT + j1]);
            float eB1 = __expf(trans[(2 * k + 1) * NT + j1]);
            PACK2(EpA[k], eA0, eA1);
            PACK2(EpB[k], eB0, eB1);
        }
    } else {
        // bwd: contraction over j (cols), outputs = rows j0/j1
#pragma unroll
        for (int k = 0; k < 32; k++) {
            float2 rA = *(const float2*)(trans + j0 * NT + 2 * k);
            float2 rB = *(const float2*)(trans + j1 * NT + 2 * k);
            PACK2(EpA[k], __expf(rA.x), __expf(rA.y));
            PACK2(EpB[k], __expf(rB.x), __expf(rB.y));
        }
    }

    const float* emb  = em + (size_t)b * NS * NT;
    const int*   mrow = mask + b * NS;
    float* myb0 = ubuf[w][0];
    float* myb1 = ubuf[w][1];

    float ua, ub;
    int eoff = 0;

    if (dir == 0) {
        // ---------------- FORWARD ----------------
        float2 st2 = *(const float2*)(startT + j0);
        float2 e0v = *(const float2*)(emb + j0);
        ua = __expf(st2.x + e0v.x);
        ub = __expf(st2.y + e0v.y);

        float2 ev[4]; int mv[4];
#pragma unroll
        for (int k = 0; k < 4; k++) {
            int s = 1 + k;
            ev[k] = *(const float2*)(emb + s * NT + j0);
            mv[k] = mrow[s];
        }

        for (int s0 = 1; s0 < MID; s0 += 4) {
#pragma unroll
            for (int k = 0; k < 4; k++) {
                int s = s0 + k;
                if (s >= MID) break;                       // uniform
                float ea = __expf(ev[k].x);
                float eb = __expf(ev[k].y);
                int   mk = mv[k];
                int   sn = s + 4;
                float2 ev_n = make_float2(0.f, 0.f); int mv_n = 0;
                if (sn < MID) { ev_n = *(const float2*)(emb + sn * NT + j0); mv_n = mrow[sn]; }

                // renormalizer from u_0 (lane 0), off the dot path
                float u0 = __shfl_sync(0xffffffffu, ua, 0);
                int   e0 = (__float_as_int(u0) >> 23) - 127;
                float sc = __int_as_float((127 - e0) << 23);   // exact 2^-e0

                float* pb = (s & 1) ? myb1 : myb0;
                *(float2*)(pb + j0) = make_float2(ua, ub);
                __syncwarp(0xffffffffu);

                float oA, oB;
                dot_full(pb, EpA, EpB, oA, oB);

                if (mk) {
                    ua = oA * sc * ea;
                    ub = oB * sc * eb;
                    eoff += e0;
                }
                ev[k] = ev_n; mv[k] = mv_n;
            }
        }
    } else {
        // ---------------- BACKWARD ----------------
        float2 en2 = *(const float2*)(endT + j0);
        ua = __expf(en2.x);                  // v_j(NS-1)
        ub = __expf(en2.y);

        float2 ev[4]; int mv[4];
#pragma unroll
        for (int k = 0; k < 4; k++) {
            int s = NS - 1 - k;
            ev[k] = *(const float2*)(emb + s * NT + j0);
            mv[k] = mrow[s];
        }

        for (int s0 = NS - 1; s0 >= MID; s0 -= 4) {
#pragma unroll
            for (int k = 0; k < 4; k++) {
                int s = s0 - k;                            // >= MID always (256 | 4)
                float ea = __expf(ev[k].x);
                float eb = __expf(ev[k].y);
                int   mk = mv[k];
                int   sn = s - 4;
                float2 ev_n = make_float2(0.f, 0.f); int mv_n = 0;
                if (sn >= MID) { ev_n = *(const float2*)(emb + sn * NT + j0); mv_n = mrow[sn]; }

                // publish w = e_s ∘ v(s)
                float wa  = ua * ea;
                float wb2 = ub * eb;
                float w0 = __shfl_sync(0xffffffffu, wa, 0);
                int   e0 = (__float_as_int(w0) >> 23) - 127;
                float sc = __int_as_float((127 - e0) << 23);

                float* pb = (s & 1) ? myb1 : myb0;
                *(float2*)(pb + j0) = make_float2(wa, wb2);
                __syncwarp(0xffffffffu);

                float oA, oB;
                dot_full(pb, EpA, EpB, oA, oB);

                if (mk) {
                    ua = oA * sc;                          // v(s-1)
                    ub = oB * sc;
                    eoff += e0;
                }
                ev[k] = ev_n; mv[k] = mv_n;
            }
        }
    }

    // midpoint vectors
    fv[bs][dir][j0] = ua;
    fv[bs][dir][j1] = ub;

    // ---- numerator partial over this warp's half of S + mask count ----
    float npart = 0.0f; int mcount = 0;
    const size_t tbase = (size_t)b * NS;
    const int sBeg = dir ? MID : 0;
    const int sEnd = dir ? NS : MID;
    for (int s = sBeg + t; s < sEnd; s += 32) {
        size_t idx = tbase + s;
        int tg = is64 ? tags32[2 * idx] : tags32[idx];
        float emv = emb[s * NT + tg];
        if (s == 0) {
            npart += startT[tg] + emv;
        } else if (mrow[s]) {
            size_t idp = tbase + s - 1;
            int tp = is64 ? tags32[2 * idp] : tags32[idp];
            npart += trans[tp * NT + tg] + emv;
        }
        mcount += (mrow[s] != 0);
    }
    npart  = warp_sum_f(npart);
    mcount = warp_sum_i(mcount);
    if (t == 0) { nsh[w] = npart; msh[w] = mcount; eosh[w] = eoff; }
    __syncthreads();

    // ---- combine: warp 0 -> batch slot 0, warp 2 -> batch slot 1 ----
    if (dir == 0) {
        float z = fv[bs][0][j0] * fv[bs][1][j0]
                + fv[bs][0][j1] * fv[bs][1][j1];
        z = warp_sum_f(z);
        if (t == 0) {
            int   etot = eosh[2 * bs] + eosh[2 * bs + 1];
            int   mc   = msh[2 * bs] + msh[2 * bs + 1];
            float ns   = nsh[2 * bs] + nsh[2 * bs + 1];
            size_t lidx = tbase + (mc - 1);
            int last = is64 ? tags32[2 * lidx] : tags32[lidx];
            ns += endT[last];
            double denom = (double)etot * 0.6931471805599453 + (double)logf(z);
            g_llh[b] = (float)(denom - (double)ns);

            __threadfence();
            int ticket = atomicAdd(&g_cnt, 1);
            if (ticket == NB - 1) {
                float acc = 0.0f;
#pragma unroll 8
                for (int i = 0; i < NB; i++) acc += __ldcg(&g_llh[i]);
                *out = acc / (float)NB;
                g_cnt = 0;                    // self-reset for graph replay
            }
        }
    }
}

extern "C" void kernel_launch(void* const* d_in, const int* in_sizes, int n_in,
                              void* d_out, int out_size)
{
    const float* em   = (const float*)d_in[0];
    const int*   tags = (const int*)d_in[1];
    const int*   mask = (const int*)d_in[2];
    const float* st   = (const float*)d_in[3];
    const float* en   = (const float*)d_in[4];
    const float* tr   = (const float*)d_in[5];

    crf_forward_kernel<<<NB / 2, 128>>>(em, tags, mask, st, en, tr, (float*)d_out);
}

// round 13
// speedup vs baseline: 1.3949x; 1.3949x over previous
#include <cuda_runtime.h>

// CRF NLL mean — B=256, S=512, T=64.
// Bidirectional split (fwd: transitions 1..255, bwd: 511..256), combined at the
// midpoint:  Z_b = sum_j f_j(255) * v_j(255) * 2^(eoff_f + eoff_b).
// Each chain = ONE self-contained warp. Block = 128 thr = 2 batches x
// {fwd,bwd}; grid = 128 -> 1 block/SM, 1 warp/SMSP.
// R13: fully branch-free 256-step steady state (fwd has a masked dummy step 0),
// FSEL-based masked updates, guard-free rotating prefetch.

constexpr int NT  = 64;
constexpr int NB  = 256;
constexpr int NS  = 512;

__device__ float g_llh[NB];
__device__ int   g_cnt = 0;

#define FMA2(d,a,b,c) asm("fma.rn.f32x2 %0, %1, %2, %3;" : "=l"(d) : "l"(a), "l"(b), "l"(c))
#define ADD2(d,a,b)   asm("add.rn.f32x2 %0, %1, %2;"     : "=l"(d) : "l"(a), "l"(b))
#define PACK2(d,lo,hi)   asm("mov.b64 %0, {%1, %2};" : "=l"(d) : "f"(lo), "f"(hi))
#define UNPACK2(lo,hi,s) asm("mov.b64 {%0, %1}, %2;" : "=f"(lo), "=f"(hi) : "l"(s))

__device__ __forceinline__ float warp_sum_f(float v) {
#pragma unroll
    for (int o = 16; o > 0; o >>= 1) v += __shfl_down_sync(0xffffffffu, v, o);
    return v;
}
__device__ __forceinline__ int warp_sum_i(int v) {
#pragma unroll
    for (int o = 16; o > 0; o >>= 1) v += __shfl_down_sync(0xffffffffu, v, o);
    return v;
}

// Full 64-contraction for outputs (j0, j1), parity-split f32x2 accumulators.
__device__ __forceinline__ void dot_full(
    const float* __restrict__ pb,
    const unsigned long long* __restrict__ EpA,
    const unsigned long long* __restrict__ EpB,
    float& outA, float& outB)
{
    unsigned long long a0=0ull,a1=0ull,a2=0ull,a3=0ull;
    unsigned long long b0=0ull,b1=0ull,b2=0ull,b3=0ull;
    const ulonglong2* p2 = (const ulonglong2*)pb;   // 16 x 16B broadcast reads
#pragma unroll
    for (int g = 0; g < 16; g += 2) {
        ulonglong2 q0 = p2[g];
        ulonglong2 q1 = p2[g + 1];
        FMA2(a0, q0.x, EpA[2*g + 0], a0);
        FMA2(b0, q0.x, EpB[2*g + 0], b0);
        FMA2(a1, q0.y, EpA[2*g + 1], a1);
        FMA2(b1, q0.y, EpB[2*g + 1], b1);
        FMA2(a2, q1.x, EpA[2*g + 2], a2);
        FMA2(b2, q1.x, EpB[2*g + 2], b2);
        FMA2(a3, q1.y, EpA[2*g + 3], a3);
        FMA2(b3, q1.y, EpB[2*g + 3], b3);
    }
    ADD2(a0, a0, a1); ADD2(a2, a2, a3); ADD2(a0, a0, a2);
    ADD2(b0, b0, b1); ADD2(b2, b2, b3); ADD2(b0, b0, b2);
    float lo, hi;
    UNPACK2(lo, hi, a0); outA = lo + hi;
    UNPACK2(lo, hi, b0); outB = lo + hi;
}

__global__ __launch_bounds__(128, 1) void crf_forward_kernel(
    const float* __restrict__ em,        // (B,S,T)
    const int*   __restrict__ tags32,    // (B,S) int32 (or int64 viewed as pairs)
    const int*   __restrict__ mask,      // (B,S)
    const float* __restrict__ startT,
    const float* __restrict__ endT,
    const float* __restrict__ trans,
    float*       __restrict__ out)
{
    const int tid = threadIdx.x;
    const int w   = tid >> 5;            // warp 0..3 -> SMSP 0..3
    const int t   = tid & 31;            // lane; owns outputs j0=2t, j1=2t+1
    const int bs  = w >> 1;              // batch slot (0/1)
    const int dir = w & 1;               // 0 = forward, 1 = backward
    const int b   = blockIdx.x * 2 + bs;

    __shared__ __align__(16) float ubuf[4][2][NT];  // per-warp double buffer
    __shared__ float fv[2][2][NT];
    __shared__ float nsh[4];
    __shared__ int   msh[4], eosh[4];

    bool is64 = true;
#pragma unroll
    for (int k = 0; k < 16; k++) is64 &= (tags32[2 * k + 1] == 0);

    const int j0 = 2 * t, j1 = 2 * t + 1;

    // E pairs over contraction dim, parity-packed (128 regs)
    unsigned long long EpA[32], EpB[32];
    if (dir == 0) {
#pragma unroll
        for (int k = 0; k < 32; k++) {
            float eA0 = __expf(trans[(2 * k)     * NT + j0]);
            float eA1 = __expf(trans[(2 * k + 1) * NT + j0]);
            float eB0 = __expf(trans[(2 * k)     * NT + j1]);
            float eB1 = __expf(trans[(2 * k + 1) * NT + j1]);
            PACK2(EpA[k], eA0, eA1);
            PACK2(EpB[k], eB0, eB1);
        }
    } else {
#pragma unroll
        for (int k = 0; k < 32; k++) {
            float2 rA = *(const float2*)(trans + j0 * NT + 2 * k);
            float2 rB = *(const float2*)(trans + j1 * NT + 2 * k);
            PACK2(EpA[k], __expf(rA.x), __expf(rA.y));
            PACK2(EpB[k], __expf(rB.x), __expf(rB.y));
        }
    }

    const float* emb  = em + (size_t)b * NS * NT;
    const int*   mrow = mask + b * NS;
    float* myb0 = ubuf[w][0];
    float* myb1 = ubuf[w][1];

    // step k (0..255) uses emission row: fwd s=k (k=0 dummy, masked off);
    // bwd s=511-k. Direction-dependent signed row stride, branch-free body.
    const int  srow0   = dir ? (NS - 1) : 0;
    const int  sstep   = dir ? -1 : 1;
    const float* ep0   = emb + srow0 * NT + j0;     // row for k=0
    const long rstride = (long)sstep * NT;          // floats per step

    float ua, ub;
    int eoff = 0;
    if (dir == 0) {
        float2 st2 = *(const float2*)(startT + j0);
        float2 e0v = *(const float2*)(emb + j0);
        ua = __expf(st2.x + e0v.x);
        ub = __expf(st2.y + e0v.y);
    } else {
        float2 en2 = *(const float2*)(endT + j0);
        ua = __expf(en2.x);
        ub = __expf(en2.y);
    }
    const int isBwd = dir;                // 0/1, used as float select below

    // depth-4 rotating prefetch (always in-bounds: rows 0..259 / 252..511)
    float2 ev[4]; int mv[4];
#pragma unroll
    for (int k = 0; k < 4; k++) {
        ev[k] = *(const float2*)(ep0 + (long)k * rstride);
        mv[k] = mrow[srow0 + k * sstep];
    }
    if (dir == 0) mv[0] = 0;              // fwd dummy step

    for (int ko = 0; ko < 64; ko++) {
#pragma unroll
        for (int kk = 0; kk < 4; kk++) {
            const int k  = 4 * ko + kk;
            const int bi = k & 1;
            float ea = __expf(ev[kk].x);
            float eb = __expf(ev[kk].y);
            int   mk = mv[kk];
            // prefetch k+4 (unconditional, always in-bounds)
            float2 ev_n = *(const float2*)(ep0 + (long)(k + 4) * rstride);
            int    mv_n = mrow[srow0 + (k + 4) * sstep];

            // renormalizer from previous-step u_0 (off the dot path)
            float u0 = __shfl_sync(0xffffffffu, ua, 0);
            int   e0 = (__float_as_int(u0) >> 23) - 127;
            float sc = __int_as_float((127 - e0) << 23);   // exact 2^-e0

            // publish: fwd publishes u, bwd publishes e_s ∘ v  (select, no branch)
            float pa = isBwd ? (ua * ea) : ua;
            float pbv = isBwd ? (ub * eb) : ub;
            float* pb = bi ? myb1 : myb0;
            *(float2*)(pb + j0) = make_float2(pa, pbv);
            __syncwarp(0xffffffffu);

            // combined output scale (off-path): fwd folds e_{s}, bwd does not
            float csA = isBwd ? sc : (sc * ea);
            float csB = isBwd ? sc : (sc * eb);

            float oA, oB;
            dot_full(pb, EpA, EpB, oA, oB);

            const bool keep = (mk != 0);
            float na = oA * csA;
            float nb = oB * csB;
            ua = keep ? na : ua;
            ub = keep ? nb : ub;
            eoff += e0 & (-mk);
            ev[kk] = ev_n; mv[kk] = mv_n;
        }
    }

    // midpoint vectors
    fv[bs][dir][j0] = ua;
    fv[bs][dir][j1] = ub;

    // ---- numerator partial over this warp's half of S + mask count ----
    float npart = 0.0f; int mcount = 0;
    const size_t tbase = (size_t)b * NS;
    const int sBeg = dir ? (NS / 2) : 0;
    const int sEnd = sBeg + NS / 2;
    for (int s = sBeg + t; s < sEnd; s += 32) {
        size_t idx = tbase + s;
        int tg = is64 ? tags32[2 * idx] : tags32[idx];
        float emv = emb[s * NT + tg];
        if (s == 0) {
            npart += startT[tg] + emv;
        } else if (mrow[s]) {
            size_t idp = tbase + s - 1;
            int tp = is64 ? tags32[2 * idp] : tags32[idp];
            npart += trans[tp * NT + tg] + emv;
        }
        mcount += (mrow[s] != 0);
    }
    npart  = warp_sum_f(npart);
    mcount = warp_sum_i(mcount);
    if (t == 0) { nsh[w] = npart; msh[w] = mcount; eosh[w] = eoff; }
    __syncthreads();

    // ---- combine: warp 0 -> batch slot 0, warp 2 -> batch slot 1 ----
    if (dir == 0) {
        float z = fv[bs][0][j0] * fv[bs][1][j0]
                + fv[bs][0][j1] * fv[bs][1][j1];
        z = warp_sum_f(z);
        if (t == 0) {
            int   etot = eosh[2 * bs] + eosh[2 * bs + 1];
            int   mc   = msh[2 * bs] + msh[2 * bs + 1];
            float ns   = nsh[2 * bs] + nsh[2 * bs + 1];
            size_t lidx = tbase + (mc - 1);
            int last = is64 ? tags32[2 * lidx] : tags32[lidx];
            ns += endT[last];
            double denom = (double)etot * 0.6931471805599453 + (double)logf(z);
            g_llh[b] = (float)(denom - (double)ns);

            __threadfence();
            int ticket = atomicAdd(&g_cnt, 1);
            if (ticket == NB - 1) {
                float acc = 0.0f;
#pragma unroll 8
                for (int i = 0; i < NB; i++) acc += __ldcg(&g_llh[i]);
                *out = acc / (float)NB;
                g_cnt = 0;                    // self-reset for graph replay
            }
        }
    }
}

extern "C" void kernel_launch(void* const* d_in, const int* in_sizes, int n_in,
                              void* d_out, int out_size)
{
    const float* em   = (const float*)d_in[0];
    const int*   tags = (const int*)d_in[1];
    const int*   mask = (const int*)d_in[2];
    const float* st   = (const float*)d_in[3];
    const float* en   = (const float*)d_in[4];
    const float* tr   = (const float*)d_in[5];

    crf_forward_kernel<<<NB / 2, 128>>>(em, tags, mask, st, en, tr, (float*)d_out);
}